// round 13
// baseline (speedup 1.0000x reference)
#include <cuda_runtime.h>
#include <cuda_fp16.h>
#include <cstdint>

#define Bsz 16
#define Cch 512
#define Nsp 1024
#define Gg  32
#define CPG 16
#define EPSf 1e-6f
#define SCALE 0.044194173824159216f   // 512^-0.5

// ---------------- scratch ----------------------------------------------------
__device__ __half g_hn[Bsz * Nsp * Cch];             // [b][n][c]
__device__ __half g_qk[Bsz * Nsp * 1024];            // [b][n][dd] dd<512:q (scaled), >=512:k
__device__ __half g_v [Bsz * Cch * Nsp];             // [b][d][n]
__device__ __half g_o [Bsz * Nsp * Cch];             // [b][n][c]
__device__ __half g_attnh[(size_t)Bsz * Nsp * Nsp];  // fp16 UNNORMALIZED probs exp(s)
__device__ float  g_rsum[Bsz * Nsp];                 // row sums of exp(s)
__device__ __half g_wt[4 * Cch * Cch];               // Wt[w][d][c] = W[c][d]; w=0 prescaled by SCALE
__device__ float  g_bqk[1024];                       // [SCALE*b0 ; b1]

// ---------------- streams/events (created pre-main, before harness baseline) -
struct AsyncRes {
    cudaStream_t s1;
    cudaEvent_t evA, ev_wt, ev_s1done;
    AsyncRes() {
        cudaStreamCreateWithFlags(&s1, cudaStreamNonBlocking);
        cudaEventCreateWithFlags(&evA,      cudaEventDisableTiming);
        cudaEventCreateWithFlags(&ev_wt,    cudaEventDisableTiming);
        cudaEventCreateWithFlags(&ev_s1done, cudaEventDisableTiming);
    }
};
static AsyncRes g_as;

// ---------------- PTX helpers (baseline ISA only: sm_80-level) ---------------
__device__ __forceinline__ uint32_t smem_u32(const void* p) {
    uint32_t a;
    asm("{ .reg .u64 t; cvta.to.shared.u64 t, %1; cvt.u32.u64 %0, t; }" : "=r"(a) : "l"(p));
    return a;
}
#define CP16(saddr, gptr) \
    asm volatile("cp.async.cg.shared.global [%0], [%1], 16;" :: "r"(saddr), "l"(gptr))
#define CPCOMMIT() asm volatile("cp.async.commit_group;")
#define CPWAIT0()  asm volatile("cp.async.wait_group 0;")
#define CPWAIT1()  asm volatile("cp.async.wait_group 1;")
#define LDSM4(r, a) \
    asm volatile("ldmatrix.sync.aligned.m8n8.x4.shared.b16 {%0,%1,%2,%3}, [%4];" \
        : "=r"((r)[0]), "=r"((r)[1]), "=r"((r)[2]), "=r"((r)[3]) : "r"(a))
#define MMA16816(d, a, b0, b1) \
    asm volatile("mma.sync.aligned.m16n8k16.row.col.f32.f16.f16.f32 " \
        "{%0,%1,%2,%3},{%4,%5,%6,%7},{%8,%9},{%0,%1,%2,%3};" \
        : "+f"((d)[0]), "+f"((d)[1]), "+f"((d)[2]), "+f"((d)[3]) \
        : "r"((a)[0]), "r"((a)[1]), "r"((a)[2]), "r"((a)[3]), "r"(b0), "r"(b1))

// ---------------- fused GroupNorm (stats + apply + transpose) ----------------
#define GN_SMEM (CPG * 1025 * 4)
__global__ void __launch_bounds__(256) gn_fused(const float* __restrict__ x,
                                                const float* __restrict__ gamma,
                                                const float* __restrict__ beta,
                                                int b0) {
    extern __shared__ float sm[];
    int b = (blockIdx.x >> 5) + b0, g = blockIdx.x & 31;
    int tid = threadIdx.x;
    const float* xp = x + (size_t)(b * Cch + g * CPG) * Nsp;

    float s = 0.f, ss = 0.f;
    for (int i = tid; i < CPG * Nsp; i += 256) {
        float v = xp[i];
        sm[(i >> 10) * 1025 + (i & 1023)] = v;
        s += v; ss += v * v;
    }
    __shared__ float shs[8], shss[8], stats[2];
    for (int o = 16; o > 0; o >>= 1) { s += __shfl_xor_sync(~0u, s, o); ss += __shfl_xor_sync(~0u, ss, o); }
    if ((tid & 31) == 0) { shs[tid >> 5] = s; shss[tid >> 5] = ss; }
    __syncthreads();
    if (tid < 8) {
        s = shs[tid]; ss = shss[tid];
        for (int o = 4; o > 0; o >>= 1) { s += __shfl_xor_sync(0xff, s, o); ss += __shfl_xor_sync(0xff, ss, o); }
        if (tid == 0) {
            float mu = s * (1.f / (CPG * Nsp));
            float var = ss * (1.f / (CPG * Nsp)) - mu * mu;
            stats[0] = mu; stats[1] = rsqrtf(var + EPSf);
        }
    }
    __syncthreads();
    float mu = stats[0], inv = stats[1];
    int c = tid & 15;
    float gam = gamma[g * CPG + c] * inv;
    float bet = beta[g * CPG + c] - mu * gam;
    __half* hb = g_hn + (size_t)b * Nsp * Cch + g * CPG;
    const float* src = sm + c * 1025;
    for (int j = tid; j < CPG * Nsp; j += 256) {
        int n = j >> 4;
        hb[(size_t)n * Cch + c] = __float2half_rn(src[n] * gam + bet);
    }
}

// ---------------- weight transpose: Wt[d][c] = fp16(sc * W[c][d]) ------------
__global__ void __launch_bounds__(256) wt_kernel(const float* __restrict__ W0, const float* __restrict__ W1,
                                                 const float* __restrict__ W2, const float* __restrict__ W3) {
    __shared__ float t[32][33];
    int w = blockIdx.z;
    const float* src = (w == 0) ? W0 : (w == 1) ? W1 : (w == 2) ? W2 : W3;
    float sc = (w == 0) ? SCALE : 1.0f;
    __half* dst = g_wt + (size_t)w * Cch * Cch;
    int c0 = blockIdx.y * 32, d0 = blockIdx.x * 32;
    int tx = threadIdx.x & 31, ty = threadIdx.x >> 5;
    #pragma unroll
    for (int i = 0; i < 4; i++)
        t[ty + i * 8][tx] = sc * src[(size_t)(c0 + ty + i * 8) * Cch + d0 + tx];
    __syncthreads();
    #pragma unroll
    for (int i = 0; i < 4; i++)
        dst[(size_t)(d0 + ty + i * 8) * Cch + c0 + tx] = __float2half_rn(t[tx][ty + i * 8]);
}

// ---------------- combined qk bias + rsum zero -------------------------------
__global__ void prep_bias(const float* __restrict__ b0, const float* __restrict__ b1) {
    int j = blockIdx.x * 256 + threadIdx.x;
    if (j < 1024) g_bqk[j] = (j < 512) ? SCALE * b0[j] : b1[j - 512];
    if (j < Bsz * Nsp) g_rsum[j] = 0.f;
}

// ---------------- mma.sync GEMM: D[m][n'] = sum_k A[m][k]*B[n'][k] -----------
// CTA 128x128, BK=64 halves (128B rows, xor-swizzled), 8 warps 32x64 each.
// 3-stage cp.async pipeline + explicit ldmatrix fragment double-buffering.
struct GArgs {
    const __half* A; const __half* B; void* D;
    const float* bias; const float* res;
    long long sA, sB, sD;
    int lda, ldb, ldd, K;
    int b0;    // global batch offset (rsum indexing only)
};

#define M_EXP    0   // fp16, exp(v); row sums atomically into g_rsum
#define M_QK     1   // fp16, v + bias[col]
#define M_V      2   // fp16, v + bias[row]
#define M_AV     3   // fp16, v * (1/rsum[row])
#define M_FINAL  4   // fp32, v + bias[row] + res

#define STAGE_BYTES 32768

template<int MODE>
__global__ void __launch_bounds__(256, 2) gemm_mma(const GArgs p) {
    extern __shared__ char smem[];
    const uint32_t sb = smem_u32(smem);
    const int tid = threadIdx.x, lane = tid & 31, wid = tid >> 5;
    const int wm = wid & 3, wn = wid >> 2;
    const int bz = blockIdx.z;
    const int M0 = blockIdx.y * 128, N0 = blockIdx.x * 128;

    // gmem->smem loader mapping: thread -> (row, 4 chunks of 16B)
    const int lr  = tid >> 1;
    const int lcb = (tid & 1) * 4;
    const __half* Ag = p.A + (long long)bz * p.sA + (long long)(M0 + lr) * p.lda;
    const __half* Bg = p.B + (long long)bz * p.sB + (long long)(N0 + lr) * p.ldb;
    const uint32_t rsw = (uint32_t)(lr & 7);
    const uint32_t sArow = sb + lr * 128;
    const uint32_t sBrow = sb + 16384 + lr * 128;

    // ldmatrix per-thread address components
    const int rA0 = wm * 32 + (lane & 15);
    const int cA0 = (lane >> 4);
    const int rB0 = wn * 64 + ((lane >> 4) << 3) + (lane & 7);
    const int cB0 = ((lane >> 3) & 1);

    float acc[2][8][4];
    #pragma unroll
    for (int i = 0; i < 2; i++)
        #pragma unroll
        for (int j = 0; j < 8; j++)
            #pragma unroll
            for (int q = 0; q < 4; q++) acc[i][j][q] = 0.f;

    const int S = p.K >> 6;

    // prefetch stages 0 and 1
    #pragma unroll
    for (int st = 0; st < 2; st++) {
        const __half* ga = Ag + st * 64;
        const __half* gb = Bg + st * 64;
        uint32_t oA = sArow + st * STAGE_BYTES;
        uint32_t oB = sBrow + st * STAGE_BYTES;
        #pragma unroll
        for (int i = 0; i < 4; i++) {
            int c = lcb + i;
            uint32_t sw = ((uint32_t)c ^ rsw) << 4;
            CP16(oA + sw, ga + c * 8);
            CP16(oB + sw, gb + c * 8);
        }
        CPCOMMIT();
    }

    uint32_t afr[2][2][4], bfr[2][4][4];

#define LOADF(ks, A0, B0, af, bf) do {                                              \
    _Pragma("unroll")                                                               \
    for (int mt = 0; mt < 2; mt++) {                                                \
        int row = rA0 + mt * 16;                                                    \
        LDSM4((af)[mt], (A0) + row * 128 +                                          \
              ((uint32_t)((cA0 + 2 * (ks)) ^ (row & 7)) << 4));                     \
    }                                                                               \
    _Pragma("unroll")                                                               \
    for (int pp = 0; pp < 4; pp++) {                                                \
        int row = rB0 + pp * 16;                                                    \
        LDSM4((bf)[pp], (B0) + row * 128 +                                          \
              ((uint32_t)((cB0 + 2 * (ks)) ^ (row & 7)) << 4));                     \
    }                                                                               \
} while (0)

    int buf = 0;
    for (int s = 0; s < S; s++) {
        if (s + 1 < S) { CPWAIT1(); } else { CPWAIT0(); }
        __syncthreads();

        // prefetch stage s+2 into the buffer freed at stage s-1
        if (s + 2 < S) {
            int nb = buf + 2; if (nb >= 3) nb -= 3;
            const __half* ga = Ag + (s + 2) * 64;
            const __half* gb = Bg + (s + 2) * 64;
            uint32_t oA = sArow + nb * STAGE_BYTES;
            uint32_t oB = sBrow + nb * STAGE_BYTES;
            #pragma unroll
            for (int i = 0; i < 4; i++) {
                int c = lcb + i;
                uint32_t sw = ((uint32_t)c ^ rsw) << 4;
                CP16(oA + sw, ga + c * 8);
                CP16(oB + sw, gb + c * 8);
            }
            CPCOMMIT();
        }

        uint32_t A0 = sb + buf * STAGE_BYTES;
        uint32_t B0 = A0 + 16384;

        LOADF(0, A0, B0, afr[0], bfr[0]);
        #pragma unroll
        for (int ks = 0; ks < 4; ks++) {
            int cur = ks & 1;
            if (ks < 3) LOADF(ks + 1, A0, B0, afr[cur ^ 1], bfr[cur ^ 1]);
            #pragma unroll
            for (int mt = 0; mt < 2; mt++)
                #pragma unroll
                for (int nt = 0; nt < 8; nt++)
                    MMA16816(acc[mt][nt], afr[cur][mt],
                             bfr[cur][nt >> 1][(nt & 1) * 2],
                             bfr[cur][nt >> 1][(nt & 1) * 2 + 1]);
        }
        buf++; if (buf >= 3) buf = 0;
    }

    // ------------- epilogue -------------
    const int mbase = M0 + wm * 32 + (lane >> 2);
    const int nbase = N0 + wn * 64 + (lane & 3) * 2;
    const int brs = (bz + p.b0) * Nsp;
    #pragma unroll
    for (int mt = 0; mt < 2; mt++) {
        int r0 = mbase + mt * 16, r1 = r0 + 8;
        float bi0 = 0.f, bi1 = 0.f;
        if (MODE == M_V || MODE == M_FINAL) { bi0 = __ldg(&p.bias[r0]); bi1 = __ldg(&p.bias[r1]); }
        if (MODE == M_AV) {
            bi0 = 1.0f / __ldg(&g_rsum[brs + r0]);
            bi1 = 1.0f / __ldg(&g_rsum[brs + r1]);
        }
        float s0 = 0.f, s1 = 0.f;   // M_EXP partial row sums
        #pragma unroll
        for (int nt = 0; nt < 8; nt++) {
            int cc = nbase + nt * 8;
            float v0 = acc[mt][nt][0], v1 = acc[mt][nt][1];
            float v2 = acc[mt][nt][2], v3 = acc[mt][nt][3];
            if (MODE == M_EXP) {
                __half* Dh = (__half*)p.D + (long long)bz * p.sD;
                float e0 = __expf(v0), e1 = __expf(v1);
                float e2 = __expf(v2), e3 = __expf(v3);
                *(__half2*)(Dh + (size_t)r0 * p.ldd + cc) = __floats2half2_rn(e0, e1);
                *(__half2*)(Dh + (size_t)r1 * p.ldd + cc) = __floats2half2_rn(e2, e3);
                s0 += e0 + e1; s1 += e2 + e3;
            } else if (MODE == M_QK) {
                __half* Dh = (__half*)p.D + (long long)bz * p.sD;
                float c0 = __ldg(&p.bias[cc]), c1 = __ldg(&p.bias[cc + 1]);
                *(__half2*)(Dh + (size_t)r0 * p.ldd + cc) = __floats2half2_rn(v0 + c0, v1 + c1);
                *(__half2*)(Dh + (size_t)r1 * p.ldd + cc) = __floats2half2_rn(v2 + c0, v3 + c1);
            } else if (MODE == M_V) {
                __half* Dh = (__half*)p.D + (long long)bz * p.sD;
                *(__half2*)(Dh + (size_t)r0 * p.ldd + cc) = __floats2half2_rn(v0 + bi0, v1 + bi0);
                *(__half2*)(Dh + (size_t)r1 * p.ldd + cc) = __floats2half2_rn(v2 + bi1, v3 + bi1);
            } else if (MODE == M_AV) {
                __half* Dh = (__half*)p.D + (long long)bz * p.sD;
                *(__half2*)(Dh + (size_t)r0 * p.ldd + cc) = __floats2half2_rn(v0 * bi0, v1 * bi0);
                *(__half2*)(Dh + (size_t)r1 * p.ldd + cc) = __floats2half2_rn(v2 * bi1, v3 * bi1);
            } else {
                float* Dp = (float*)p.D + (long long)bz * p.sD;
                const float* Rp = p.res + (long long)bz * p.sD;
                float2 x0 = *(const float2*)(Rp + (size_t)r0 * p.ldd + cc);
                float2 x1 = *(const float2*)(Rp + (size_t)r1 * p.ldd + cc);
                *(float2*)(Dp + (size_t)r0 * p.ldd + cc) = make_float2(v0 + bi0 + x0.x, v1 + bi0 + x0.y);
                *(float2*)(Dp + (size_t)r1 * p.ldd + cc) = make_float2(v2 + bi1 + x1.x, v3 + bi1 + x1.y);
            }
        }
        if (MODE == M_EXP) {
            s0 += __shfl_xor_sync(~0u, s0, 1); s0 += __shfl_xor_sync(~0u, s0, 2);
            s1 += __shfl_xor_sync(~0u, s1, 1); s1 += __shfl_xor_sync(~0u, s1, 2);
            if ((lane & 3) == 0) {
                atomicAdd(&g_rsum[brs + r0], s0);
                atomicAdd(&g_rsum[brs + r1], s1);
            }
        }
    }
}

// ---------------- launch -----------------------------------------------------
#define GEMM_SMEM (3 * STAGE_BYTES)
#define BH 8   // batches per stream half

extern "C" void kernel_launch(void* const* d_in, const int* in_sizes, int n_in,
                              void* d_out, int out_size) {
    const float* x     = (const float*)d_in[0];
    const float* gamma = (const float*)d_in[1];
    const float* beta  = (const float*)d_in[2];
    const float* W0 = (const float*)d_in[3];  const float* b0 = (const float*)d_in[4];
    const float* W1 = (const float*)d_in[5];  const float* b1 = (const float*)d_in[6];
    const float* W2 = (const float*)d_in[7];  const float* b2 = (const float*)d_in[8];
    const float* W3 = (const float*)d_in[9];  const float* b3 = (const float*)d_in[10];
    float* out = (float*)d_out;

    void *hn_, *qk_, *v_, *o_, *attnh_, *wt_, *bqk_;
    cudaGetSymbolAddress(&hn_, g_hn);
    cudaGetSymbolAddress(&qk_, g_qk);
    cudaGetSymbolAddress(&v_, g_v);
    cudaGetSymbolAddress(&o_, g_o);
    cudaGetSymbolAddress(&attnh_, g_attnh);
    cudaGetSymbolAddress(&wt_, g_wt);
    cudaGetSymbolAddress(&bqk_, g_bqk);
    const __half* hn = (const __half*)hn_;
    const __half* qk = (const __half*)qk_;
    const __half* v  = (const __half*)v_;
    const __half* o  = (const __half*)o_;
    const __half* attnh = (const __half*)attnh_;
    const __half* wt = (const __half*)wt_;
    const float* bqk = (const float*)bqk_;

    cudaFuncSetAttribute(gn_fused,           cudaFuncAttributeMaxDynamicSharedMemorySize, GN_SMEM);
    cudaFuncSetAttribute(gemm_mma<M_EXP>,    cudaFuncAttributeMaxDynamicSharedMemorySize, GEMM_SMEM);
    cudaFuncSetAttribute(gemm_mma<M_QK>,     cudaFuncAttributeMaxDynamicSharedMemorySize, GEMM_SMEM);
    cudaFuncSetAttribute(gemm_mma<M_V>,      cudaFuncAttributeMaxDynamicSharedMemorySize, GEMM_SMEM);
    cudaFuncSetAttribute(gemm_mma<M_AV>,     cudaFuncAttributeMaxDynamicSharedMemorySize, GEMM_SMEM);
    cudaFuncSetAttribute(gemm_mma<M_FINAL>,  cudaFuncAttributeMaxDynamicSharedMemorySize, GEMM_SMEM);

    const long long SNC = (long long)Nsp * Cch;      // 524288
    const long long SQK = (long long)Nsp * 1024;     // 1048576
    const long long SNN = (long long)Nsp * Nsp;      // 1048576

    cudaStream_t s1 = g_as.s1;

    // fork
    cudaEventRecord(g_as.evA, 0);
    cudaStreamWaitEvent(s1, g_as.evA, 0);

    // s1: weight transpose + bias/rsum prep, then batches 8-15 chain
    wt_kernel<<<dim3(16, 16, 4), 256, 0, s1>>>(W0, W1, W2, W3);
    prep_bias<<<64, 256, 0, s1>>>(b0, b1);
    cudaEventRecord(g_as.ev_wt, s1);

    // origin: GN for batches 0-7   |   s1: GN for batches 8-15
    gn_fused<<<BH * Gg, 256, GN_SMEM>>>(x, gamma, beta, 0);
    gn_fused<<<BH * Gg, 256, GN_SMEM, s1>>>(x, gamma, beta, BH);

    // origin needs wt/bqk/rsum from s1 before its GEMMs
    cudaStreamWaitEvent(0, g_as.ev_wt, 0);

    GArgs a;
    // ---------- per-half chains (h=0 on origin, h=1 on s1) ----------
    for (int h = 0; h < 2; h++) {
        cudaStream_t st = h ? s1 : (cudaStream_t)0;
        int boff = h * BH;
        const __half* hnb = hn + (long long)boff * SNC;
        const __half* qkb = qk + (long long)boff * SQK;
        const __half* vb  = v  + (long long)boff * SNC;
        const __half* ob  = o  + (long long)boff * SNC;
        const __half* ahb = attnh + (long long)boff * SNN;

        // qk = hn @ [SCALE*W0t ; W1t]^T + bqk
        a = { hnb, wt, (void*)qkb, bqk, nullptr,
              SNC, 0, SQK, Cch, Cch, 1024, Cch, boff };
        gemm_mma<M_QK><<<dim3(8, 8, BH), 256, GEMM_SMEM, st>>>(a);
        // v[d][n] = W2t @ hn^T + b2[d]
        a = { wt + (size_t)2 * Cch * Cch, hnb, (void*)vb, b2, nullptr,
              0, SNC, SNC, Cch, Cch, Nsp, Cch, boff };
        gemm_mma<M_V><<<dim3(8, 4, BH), 256, GEMM_SMEM, st>>>(a);
        // attnh = exp(q @ k^T); rsum accumulated
        a = { qkb, qkb + 512, (void*)ahb, nullptr, nullptr,
              SQK, SQK, SNN, 1024, 1024, Nsp, Cch, boff };
        gemm_mma<M_EXP><<<dim3(8, 8, BH), 256, GEMM_SMEM, st>>>(a);
        // o = (attnh @ v^T) / rsum
        a = { ahb, vb, (void*)ob, nullptr, nullptr,
              SNN, SNC, SNC, Nsp, Nsp, Cch, Nsp, boff };
        gemm_mma<M_AV><<<dim3(4, 8, BH), 256, GEMM_SMEM, st>>>(a);
        // out = W3t @ o^T + b3 + x
        a = { wt + (size_t)3 * Cch * Cch, ob, (void*)(out + (long long)boff * SNC), b3,
              x + (long long)boff * SNC,
              0, SNC, SNC, Cch, Cch, Nsp, Cch, boff };
        gemm_mma<M_FINAL><<<dim3(8, 4, BH), 256, GEMM_SMEM, st>>>(a);
    }

    // join s1 back into origin
    cudaEventRecord(g_as.ev_s1done, s1);
    cudaStreamWaitEvent(0, g_as.ev_s1done, 0);
}

// round 14
// speedup vs baseline: 1.4788x; 1.4788x over previous
#include <cuda_runtime.h>
#include <cuda_fp16.h>
#include <cstdint>

#define Bsz 16
#define Cch 512
#define Nsp 1024
#define Gg  32
#define CPG 16
#define EPSf 1e-6f
#define SCALE 0.044194173824159216f   // 512^-0.5

// ---------------- scratch ----------------------------------------------------
__device__ __half g_hn[Bsz * Nsp * Cch];             // [b][n][c]
__device__ __half g_qk[Bsz * Nsp * 1024];            // [b][n][dd] dd<512:q (scaled), >=512:k
__device__ __half g_v [Bsz * Cch * Nsp];             // [b][d][n]
__device__ __half g_o [Bsz * Nsp * Cch];             // [b][n][c]
__device__ __half g_attnh[(size_t)Bsz * Nsp * Nsp];  // fp16 UNNORMALIZED probs exp(s)
__device__ float  g_rsum[Bsz * Nsp];                 // row sums of exp(s)
__device__ __half g_wt[4 * Cch * Cch];               // Wt[w][d][c] = W[c][d]; w=0 prescaled by SCALE
__device__ float  g_bqk[1024];                       // [SCALE*b0 ; b1]

// ---------------- streams/events (created pre-main, before harness baseline) -
struct AsyncRes {
    cudaStream_t s1;
    cudaEvent_t evA, ev_wt, ev_gn, ev_v, ev_exp, ev_s1done;
    AsyncRes() {
        cudaStreamCreateWithFlags(&s1, cudaStreamNonBlocking);
        cudaEventCreateWithFlags(&evA,       cudaEventDisableTiming);
        cudaEventCreateWithFlags(&ev_wt,     cudaEventDisableTiming);
        cudaEventCreateWithFlags(&ev_gn,     cudaEventDisableTiming);
        cudaEventCreateWithFlags(&ev_v,      cudaEventDisableTiming);
        cudaEventCreateWithFlags(&ev_exp,    cudaEventDisableTiming);
        cudaEventCreateWithFlags(&ev_s1done, cudaEventDisableTiming);
    }
};
static AsyncRes g_as;

// ---------------- PTX helpers (baseline ISA only: sm_80-level) ---------------
__device__ __forceinline__ uint32_t smem_u32(const void* p) {
    uint32_t a;
    asm("{ .reg .u64 t; cvta.to.shared.u64 t, %1; cvt.u32.u64 %0, t; }" : "=r"(a) : "l"(p));
    return a;
}
#define CP16(saddr, gptr) \
    asm volatile("cp.async.cg.shared.global [%0], [%1], 16;" :: "r"(saddr), "l"(gptr))
#define CPCOMMIT() asm volatile("cp.async.commit_group;")
#define CPWAIT0()  asm volatile("cp.async.wait_group 0;")
#define CPWAIT1()  asm volatile("cp.async.wait_group 1;")
#define LDSM4(r, a) \
    asm volatile("ldmatrix.sync.aligned.m8n8.x4.shared.b16 {%0,%1,%2,%3}, [%4];" \
        : "=r"((r)[0]), "=r"((r)[1]), "=r"((r)[2]), "=r"((r)[3]) : "r"(a))
#define MMA16816(d, a, b0, b1) \
    asm volatile("mma.sync.aligned.m16n8k16.row.col.f32.f16.f16.f32 " \
        "{%0,%1,%2,%3},{%4,%5,%6,%7},{%8,%9},{%0,%1,%2,%3};" \
        : "+f"((d)[0]), "+f"((d)[1]), "+f"((d)[2]), "+f"((d)[3]) \
        : "r"((a)[0]), "r"((a)[1]), "r"((a)[2]), "r"((a)[3]), "r"(b0), "r"(b1))

// ---------------- fused GroupNorm (stats + apply + transpose) ----------------
#define GN_SMEM (CPG * 1025 * 4)
__global__ void __launch_bounds__(256) gn_fused(const float* __restrict__ x,
                                                const float* __restrict__ gamma,
                                                const float* __restrict__ beta) {
    extern __shared__ float sm[];
    int b = blockIdx.x >> 5, g = blockIdx.x & 31;
    int tid = threadIdx.x;
    const float* xp = x + (size_t)(b * Cch + g * CPG) * Nsp;

    float s = 0.f, ss = 0.f;
    for (int i = tid; i < CPG * Nsp; i += 256) {
        float v = xp[i];
        sm[(i >> 10) * 1025 + (i & 1023)] = v;
        s += v; ss += v * v;
    }
    __shared__ float shs[8], shss[8], stats[2];
    for (int o = 16; o > 0; o >>= 1) { s += __shfl_xor_sync(~0u, s, o); ss += __shfl_xor_sync(~0u, ss, o); }
    if ((tid & 31) == 0) { shs[tid >> 5] = s; shss[tid >> 5] = ss; }
    __syncthreads();
    if (tid < 8) {
        s = shs[tid]; ss = shss[tid];
        for (int o = 4; o > 0; o >>= 1) { s += __shfl_xor_sync(0xff, s, o); ss += __shfl_xor_sync(0xff, ss, o); }
        if (tid == 0) {
            float mu = s * (1.f / (CPG * Nsp));
            float var = ss * (1.f / (CPG * Nsp)) - mu * mu;
            stats[0] = mu; stats[1] = rsqrtf(var + EPSf);
        }
    }
    __syncthreads();
    float mu = stats[0], inv = stats[1];
    int c = tid & 15;
    float gam = gamma[g * CPG + c] * inv;
    float bet = beta[g * CPG + c] - mu * gam;
    __half* hb = g_hn + (size_t)b * Nsp * Cch + g * CPG;
    const float* src = sm + c * 1025;
    for (int j = tid; j < CPG * Nsp; j += 256) {
        int n = j >> 4;
        hb[(size_t)n * Cch + c] = __float2half_rn(src[n] * gam + bet);
    }
}

// ---------------- weight transpose: Wt[d][c] = fp16(sc * W[c][d]) ------------
__global__ void __launch_bounds__(256) wt_kernel(const float* __restrict__ W0, const float* __restrict__ W1,
                                                 const float* __restrict__ W2, const float* __restrict__ W3) {
    __shared__ float t[32][33];
    int w = blockIdx.z;
    const float* src = (w == 0) ? W0 : (w == 1) ? W1 : (w == 2) ? W2 : W3;
    float sc = (w == 0) ? SCALE : 1.0f;
    __half* dst = g_wt + (size_t)w * Cch * Cch;
    int c0 = blockIdx.y * 32, d0 = blockIdx.x * 32;
    int tx = threadIdx.x & 31, ty = threadIdx.x >> 5;
    #pragma unroll
    for (int i = 0; i < 4; i++)
        t[ty + i * 8][tx] = sc * src[(size_t)(c0 + ty + i * 8) * Cch + d0 + tx];
    __syncthreads();
    #pragma unroll
    for (int i = 0; i < 4; i++)
        dst[(size_t)(d0 + ty + i * 8) * Cch + c0 + tx] = __float2half_rn(t[tx][ty + i * 8]);
}

// ---------------- combined qk bias + rsum zero -------------------------------
__global__ void prep_bias(const float* __restrict__ b0, const float* __restrict__ b1) {
    int j = blockIdx.x * 256 + threadIdx.x;
    if (j < 1024) g_bqk[j] = (j < 512) ? SCALE * b0[j] : b1[j - 512];
    if (j < Bsz * Nsp) g_rsum[j] = 0.f;
}

// ---------------- mma.sync GEMM: D[m][n'] = sum_k A[m][k]*B[n'][k] -----------
// CTA 128x128, BK=64 halves (128B rows, xor-swizzled), 8 warps 32x64 each.
// 3-stage cp.async pipeline + explicit ldmatrix fragment double-buffering.
struct GArgs {
    const __half* A; const __half* B; void* D;
    const float* bias; const float* res;
    long long sA, sB, sD;
    int lda, ldb, ldd, K;
    int b0;    // global batch offset (rsum indexing only)
};

#define M_EXP    0   // fp16, exp(v); row sums atomically into g_rsum
#define M_QK     1   // fp16, v + bias[col]
#define M_V      2   // fp16, v + bias[row]
#define M_AV     3   // fp16, v * (1/rsum[row])
#define M_FINAL  4   // fp32, v + bias[row] + res

#define STAGE_BYTES 32768

template<int MODE>
__global__ void __launch_bounds__(256, 2) gemm_mma(const GArgs p) {
    extern __shared__ char smem[];
    const uint32_t sb = smem_u32(smem);
    const int tid = threadIdx.x, lane = tid & 31, wid = tid >> 5;
    const int wm = wid & 3, wn = wid >> 2;
    const int bz = blockIdx.z;
    const int M0 = blockIdx.y * 128, N0 = blockIdx.x * 128;

    // gmem->smem loader mapping: thread -> (row, 4 chunks of 16B)
    const int lr  = tid >> 1;
    const int lcb = (tid & 1) * 4;
    const __half* Ag = p.A + (long long)bz * p.sA + (long long)(M0 + lr) * p.lda;
    const __half* Bg = p.B + (long long)bz * p.sB + (long long)(N0 + lr) * p.ldb;
    const uint32_t rsw = (uint32_t)(lr & 7);
    const uint32_t sArow = sb + lr * 128;
    const uint32_t sBrow = sb + 16384 + lr * 128;

    // ldmatrix per-thread address components
    const int rA0 = wm * 32 + (lane & 15);
    const int cA0 = (lane >> 4);
    const int rB0 = wn * 64 + ((lane >> 4) << 3) + (lane & 7);
    const int cB0 = ((lane >> 3) & 1);

    float acc[2][8][4];
    #pragma unroll
    for (int i = 0; i < 2; i++)
        #pragma unroll
        for (int j = 0; j < 8; j++)
            #pragma unroll
            for (int q = 0; q < 4; q++) acc[i][j][q] = 0.f;

    const int S = p.K >> 6;

    // prefetch stages 0 and 1
    #pragma unroll
    for (int st = 0; st < 2; st++) {
        const __half* ga = Ag + st * 64;
        const __half* gb = Bg + st * 64;
        uint32_t oA = sArow + st * STAGE_BYTES;
        uint32_t oB = sBrow + st * STAGE_BYTES;
        #pragma unroll
        for (int i = 0; i < 4; i++) {
            int c = lcb + i;
            uint32_t sw = ((uint32_t)c ^ rsw) << 4;
            CP16(oA + sw, ga + c * 8);
            CP16(oB + sw, gb + c * 8);
        }
        CPCOMMIT();
    }

    uint32_t afr[2][2][4], bfr[2][4][4];

#define LOADF(ks, A0, B0, af, bf) do {                                              \
    _Pragma("unroll")                                                               \
    for (int mt = 0; mt < 2; mt++) {                                                \
        int row = rA0 + mt * 16;                                                    \
        LDSM4((af)[mt], (A0) + row * 128 +                                          \
              ((uint32_t)((cA0 + 2 * (ks)) ^ (row & 7)) << 4));                     \
    }                                                                               \
    _Pragma("unroll")                                                               \
    for (int pp = 0; pp < 4; pp++) {                                                \
        int row = rB0 + pp * 16;                                                    \
        LDSM4((bf)[pp], (B0) + row * 128 +                                          \
              ((uint32_t)((cB0 + 2 * (ks)) ^ (row & 7)) << 4));                     \
    }                                                                               \
} while (0)

    int buf = 0;
    for (int s = 0; s < S; s++) {
        if (s + 1 < S) { CPWAIT1(); } else { CPWAIT0(); }
        __syncthreads();

        // prefetch stage s+2 into the buffer freed at stage s-1
        if (s + 2 < S) {
            int nb = buf + 2; if (nb >= 3) nb -= 3;
            const __half* ga = Ag + (s + 2) * 64;
            const __half* gb = Bg + (s + 2) * 64;
            uint32_t oA = sArow + nb * STAGE_BYTES;
            uint32_t oB = sBrow + nb * STAGE_BYTES;
            #pragma unroll
            for (int i = 0; i < 4; i++) {
                int c = lcb + i;
                uint32_t sw = ((uint32_t)c ^ rsw) << 4;
                CP16(oA + sw, ga + c * 8);
                CP16(oB + sw, gb + c * 8);
            }
            CPCOMMIT();
        }

        uint32_t A0 = sb + buf * STAGE_BYTES;
        uint32_t B0 = A0 + 16384;

        LOADF(0, A0, B0, afr[0], bfr[0]);
        #pragma unroll
        for (int ks = 0; ks < 4; ks++) {
            int cur = ks & 1;
            if (ks < 3) LOADF(ks + 1, A0, B0, afr[cur ^ 1], bfr[cur ^ 1]);
            #pragma unroll
            for (int mt = 0; mt < 2; mt++)
                #pragma unroll
                for (int nt = 0; nt < 8; nt++)
                    MMA16816(acc[mt][nt], afr[cur][mt],
                             bfr[cur][nt >> 1][(nt & 1) * 2],
                             bfr[cur][nt >> 1][(nt & 1) * 2 + 1]);
        }
        buf++; if (buf >= 3) buf = 0;
    }

    // ------------- epilogue -------------
    const int mbase = M0 + wm * 32 + (lane >> 2);
    const int nbase = N0 + wn * 64 + (lane & 3) * 2;
    const int brs = (bz + p.b0) * Nsp;
    #pragma unroll
    for (int mt = 0; mt < 2; mt++) {
        int r0 = mbase + mt * 16, r1 = r0 + 8;
        float bi0 = 0.f, bi1 = 0.f;
        if (MODE == M_V || MODE == M_FINAL) { bi0 = __ldg(&p.bias[r0]); bi1 = __ldg(&p.bias[r1]); }
        if (MODE == M_AV) {
            bi0 = 1.0f / __ldg(&g_rsum[brs + r0]);
            bi1 = 1.0f / __ldg(&g_rsum[brs + r1]);
        }
        float s0 = 0.f, s1 = 0.f;   // M_EXP partial row sums
        #pragma unroll
        for (int nt = 0; nt < 8; nt++) {
            int cc = nbase + nt * 8;
            float v0 = acc[mt][nt][0], v1 = acc[mt][nt][1];
            float v2 = acc[mt][nt][2], v3 = acc[mt][nt][3];
            if (MODE == M_EXP) {
                __half* Dh = (__half*)p.D + (long long)bz * p.sD;
                float e0 = __expf(v0), e1 = __expf(v1);
                float e2 = __expf(v2), e3 = __expf(v3);
                *(__half2*)(Dh + (size_t)r0 * p.ldd + cc) = __floats2half2_rn(e0, e1);
                *(__half2*)(Dh + (size_t)r1 * p.ldd + cc) = __floats2half2_rn(e2, e3);
                s0 += e0 + e1; s1 += e2 + e3;
            } else if (MODE == M_QK) {
                __half* Dh = (__half*)p.D + (long long)bz * p.sD;
                float c0 = __ldg(&p.bias[cc]), c1 = __ldg(&p.bias[cc + 1]);
                *(__half2*)(Dh + (size_t)r0 * p.ldd + cc) = __floats2half2_rn(v0 + c0, v1 + c1);
                *(__half2*)(Dh + (size_t)r1 * p.ldd + cc) = __floats2half2_rn(v2 + c0, v3 + c1);
            } else if (MODE == M_V) {
                __half* Dh = (__half*)p.D + (long long)bz * p.sD;
                *(__half2*)(Dh + (size_t)r0 * p.ldd + cc) = __floats2half2_rn(v0 + bi0, v1 + bi0);
                *(__half2*)(Dh + (size_t)r1 * p.ldd + cc) = __floats2half2_rn(v2 + bi1, v3 + bi1);
            } else if (MODE == M_AV) {
                __half* Dh = (__half*)p.D + (long long)bz * p.sD;
                *(__half2*)(Dh + (size_t)r0 * p.ldd + cc) = __floats2half2_rn(v0 * bi0, v1 * bi0);
                *(__half2*)(Dh + (size_t)r1 * p.ldd + cc) = __floats2half2_rn(v2 * bi1, v3 * bi1);
            } else {
                float* Dp = (float*)p.D + (long long)bz * p.sD;
                const float* Rp = p.res + (long long)bz * p.sD;
                float2 x0 = *(const float2*)(Rp + (size_t)r0 * p.ldd + cc);
                float2 x1 = *(const float2*)(Rp + (size_t)r1 * p.ldd + cc);
                *(float2*)(Dp + (size_t)r0 * p.ldd + cc) = make_float2(v0 + bi0 + x0.x, v1 + bi0 + x0.y);
                *(float2*)(Dp + (size_t)r1 * p.ldd + cc) = make_float2(v2 + bi1 + x1.x, v3 + bi1 + x1.y);
            }
        }
        if (MODE == M_EXP) {
            s0 += __shfl_xor_sync(~0u, s0, 1); s0 += __shfl_xor_sync(~0u, s0, 2);
            s1 += __shfl_xor_sync(~0u, s1, 1); s1 += __shfl_xor_sync(~0u, s1, 2);
            if ((lane & 3) == 0) {
                atomicAdd(&g_rsum[brs + r0], s0);
                atomicAdd(&g_rsum[brs + r1], s1);
            }
        }
    }
}

// ---------------- launch -----------------------------------------------------
#define GEMM_SMEM (3 * STAGE_BYTES)
#define BH 8   // batches per half (AV/FINAL pipelining only)

extern "C" void kernel_launch(void* const* d_in, const int* in_sizes, int n_in,
                              void* d_out, int out_size) {
    const float* x     = (const float*)d_in[0];
    const float* gamma = (const float*)d_in[1];
    const float* beta  = (const float*)d_in[2];
    const float* W0 = (const float*)d_in[3];  const float* b0 = (const float*)d_in[4];
    const float* W1 = (const float*)d_in[5];  const float* b1 = (const float*)d_in[6];
    const float* W2 = (const float*)d_in[7];  const float* b2 = (const float*)d_in[8];
    const float* W3 = (const float*)d_in[9];  const float* b3 = (const float*)d_in[10];
    float* out = (float*)d_out;

    void *hn_, *qk_, *v_, *o_, *attnh_, *wt_, *bqk_;
    cudaGetSymbolAddress(&hn_, g_hn);
    cudaGetSymbolAddress(&qk_, g_qk);
    cudaGetSymbolAddress(&v_, g_v);
    cudaGetSymbolAddress(&o_, g_o);
    cudaGetSymbolAddress(&attnh_, g_attnh);
    cudaGetSymbolAddress(&wt_, g_wt);
    cudaGetSymbolAddress(&bqk_, g_bqk);
    const __half* hn = (const __half*)hn_;
    const __half* qk = (const __half*)qk_;
    const __half* v  = (const __half*)v_;
    const __half* o  = (const __half*)o_;
    const __half* attnh = (const __half*)attnh_;
    const __half* wt = (const __half*)wt_;
    const float* bqk = (const float*)bqk_;

    cudaFuncSetAttribute(gn_fused,           cudaFuncAttributeMaxDynamicSharedMemorySize, GN_SMEM);
    cudaFuncSetAttribute(gemm_mma<M_EXP>,    cudaFuncAttributeMaxDynamicSharedMemorySize, GEMM_SMEM);
    cudaFuncSetAttribute(gemm_mma<M_QK>,     cudaFuncAttributeMaxDynamicSharedMemorySize, GEMM_SMEM);
    cudaFuncSetAttribute(gemm_mma<M_V>,      cudaFuncAttributeMaxDynamicSharedMemorySize, GEMM_SMEM);
    cudaFuncSetAttribute(gemm_mma<M_AV>,     cudaFuncAttributeMaxDynamicSharedMemorySize, GEMM_SMEM);
    cudaFuncSetAttribute(gemm_mma<M_FINAL>,  cudaFuncAttributeMaxDynamicSharedMemorySize, GEMM_SMEM);

    const long long SNC = (long long)Nsp * Cch;      // 524288
    const long long SQK = (long long)Nsp * 1024;     // 1048576
    const long long SNN = (long long)Nsp * Nsp;      // 1048576

    cudaStream_t s1 = g_as.s1;

    // fork: s1 joins the capture via event from origin stream
    cudaEventRecord(g_as.evA, 0);
    cudaStreamWaitEvent(s1, g_as.evA, 0);

    // s1: weight transpose + bias/rsum prep (independent of x)
    wt_kernel<<<dim3(16, 16, 4), 256, 0, s1>>>(W0, W1, W2, W3);
    prep_bias<<<64, 256, 0, s1>>>(b0, b1);
    cudaEventRecord(g_as.ev_wt, s1);

    // origin: GroupNorm (all batches)
    gn_fused<<<Bsz * Gg, 256, GN_SMEM>>>(x, gamma, beta);
    cudaEventRecord(g_as.ev_gn, 0);

    GArgs a;

    // s1: v[d][n] = W2t @ hn^T + b2[d]  (needs wt [in s1 order] + hn)
    cudaStreamWaitEvent(s1, g_as.ev_gn, 0);
    a = { wt + (size_t)2 * Cch * Cch, hn, (void*)v, b2, nullptr,
          0, SNC, SNC, Cch, Cch, Nsp, Cch, 0 };
    gemm_mma<M_V><<<dim3(8, 4, Bsz), 256, GEMM_SMEM, s1>>>(a);
    cudaEventRecord(g_as.ev_v, s1);

    // origin: qk projection (needs hn [in-order] + wt/bqk/rsum from s1)
    cudaStreamWaitEvent(0, g_as.ev_wt, 0);
    a = { hn, wt, (void*)qk, bqk, nullptr,
          SNC, 0, SQK, Cch, Cch, 1024, Cch, 0 };
    gemm_mma<M_QK><<<dim3(8, 8, Bsz), 256, GEMM_SMEM>>>(a);

    // origin: attnh = exp(q @ k^T); rsum accumulated
    a = { qk, qk + 512, (void*)attnh, nullptr, nullptr,
          SQK, SQK, SNN, 1024, 1024, Nsp, Cch, 0 };
    gemm_mma<M_EXP><<<dim3(8, 8, Bsz), 256, GEMM_SMEM>>>(a);
    cudaEventRecord(g_as.ev_exp, 0);

    // ---- AV/FINAL pipelined across batch halves ----
    // origin: half 0 (needs v from s1)
    cudaStreamWaitEvent(0, g_as.ev_v, 0);
    a = { attnh, v, (void*)o, nullptr, nullptr,
          SNN, SNC, SNC, Nsp, Nsp, Cch, Nsp, 0 };
    gemm_mma<M_AV><<<dim3(4, 8, BH), 256, GEMM_SMEM>>>(a);
    a = { wt + (size_t)3 * Cch * Cch, o, (void*)out, b3, x,
          0, SNC, SNC, Cch, Cch, Nsp, Cch, 0 };
    gemm_mma<M_FINAL><<<dim3(8, 4, BH), 256, GEMM_SMEM>>>(a);

    // s1: half 1 (v in-stream; needs attnh/rsum from origin's EXP)
    cudaStreamWaitEvent(s1, g_as.ev_exp, 0);
    a = { attnh + (long long)BH * SNN, v + (long long)BH * SNC,
          (void*)(o + (long long)BH * SNC), nullptr, nullptr,
          SNN, SNC, SNC, Nsp, Nsp, Cch, Nsp, BH };
    gemm_mma<M_AV><<<dim3(4, 8, BH), 256, GEMM_SMEM, s1>>>(a);
    a = { wt + (size_t)3 * Cch * Cch, o + (long long)BH * SNC,
          (void*)(out + (long long)BH * SNC), b3, x + (long long)BH * SNC,
          0, SNC, SNC, Cch, Cch, Nsp, Cch, BH };
    gemm_mma<M_FINAL><<<dim3(8, 4, BH), 256, GEMM_SMEM, s1>>>(a);

    // join s1 back into origin
    cudaEventRecord(g_as.ev_s1done, s1);
    cudaStreamWaitEvent(0, g_as.ev_s1done, 0);
}

// round 15
// speedup vs baseline: 1.5096x; 1.0208x over previous
#include <cuda_runtime.h>
#include <cuda_fp16.h>
#include <cstdint>

#define Bsz 16
#define Cch 512
#define Nsp 1024
#define Gg  32
#define CPG 16
#define EPSf 1e-6f
#define SCALE 0.044194173824159216f   // 512^-0.5

// ---------------- scratch ----------------------------------------------------
__device__ __half g_hn[Bsz * Nsp * Cch];             // [b][n][c]
__device__ __half g_qk[Bsz * Nsp * 1024];            // [b][n][dd] dd<512:q (scaled), >=512:k
__device__ __half g_v [Bsz * Cch * Nsp];             // [b][d][n]
__device__ __half g_o [Bsz * Nsp * Cch];             // [b][n][c]
__device__ __half g_attnh[(size_t)Bsz * Nsp * Nsp];  // fp16 UNNORMALIZED probs exp(s)
__device__ float  g_rsum[Bsz * Nsp];                 // row sums of exp(s)
__device__ __half g_wt[4 * Cch * Cch];               // Wt[w][d][c] = W[c][d]; w=0 prescaled by SCALE
__device__ float  g_bqk[1024];                       // [SCALE*b0 ; b1]

// ---------------- streams/events (created pre-main, before harness baseline) -
struct AsyncRes {
    cudaStream_t s1;
    cudaEvent_t evA, ev_wt, ev_gn, ev_v, ev_qk, ev_s1done;
    AsyncRes() {
        cudaStreamCreateWithFlags(&s1, cudaStreamNonBlocking);
        cudaEventCreateWithFlags(&evA,       cudaEventDisableTiming);
        cudaEventCreateWithFlags(&ev_wt,     cudaEventDisableTiming);
        cudaEventCreateWithFlags(&ev_gn,     cudaEventDisableTiming);
        cudaEventCreateWithFlags(&ev_v,      cudaEventDisableTiming);
        cudaEventCreateWithFlags(&ev_qk,     cudaEventDisableTiming);
        cudaEventCreateWithFlags(&ev_s1done, cudaEventDisableTiming);
    }
};
static AsyncRes g_as;

// ---------------- PTX helpers (baseline ISA only: sm_80-level) ---------------
__device__ __forceinline__ uint32_t smem_u32(const void* p) {
    uint32_t a;
    asm("{ .reg .u64 t; cvta.to.shared.u64 t, %1; cvt.u32.u64 %0, t; }" : "=r"(a) : "l"(p));
    return a;
}
#define CP16(saddr, gptr) \
    asm volatile("cp.async.cg.shared.global [%0], [%1], 16;" :: "r"(saddr), "l"(gptr))
#define CPCOMMIT() asm volatile("cp.async.commit_group;")
#define CPWAIT0()  asm volatile("cp.async.wait_group 0;")
#define CPWAIT1()  asm volatile("cp.async.wait_group 1;")
#define LDSM4(r, a) \
    asm volatile("ldmatrix.sync.aligned.m8n8.x4.shared.b16 {%0,%1,%2,%3}, [%4];" \
        : "=r"((r)[0]), "=r"((r)[1]), "=r"((r)[2]), "=r"((r)[3]) : "r"(a))
#define MMA16816(d, a, b0, b1) \
    asm volatile("mma.sync.aligned.m16n8k16.row.col.f32.f16.f16.f32 " \
        "{%0,%1,%2,%3},{%4,%5,%6,%7},{%8,%9},{%0,%1,%2,%3};" \
        : "+f"((d)[0]), "+f"((d)[1]), "+f"((d)[2]), "+f"((d)[3]) \
        : "r"((a)[0]), "r"((a)[1]), "r"((a)[2]), "r"((a)[3]), "r"(b0), "r"(b1))

// ---------------- fused GroupNorm (stats + apply + transpose) ----------------
#define GN_SMEM (CPG * 1025 * 4)
__global__ void __launch_bounds__(256) gn_fused(const float* __restrict__ x,
                                                const float* __restrict__ gamma,
                                                const float* __restrict__ beta) {
    extern __shared__ float sm[];
    int b = blockIdx.x >> 5, g = blockIdx.x & 31;
    int tid = threadIdx.x;
    const float* xp = x + (size_t)(b * Cch + g * CPG) * Nsp;

    float s = 0.f, ss = 0.f;
    for (int i = tid; i < CPG * Nsp; i += 256) {
        float v = xp[i];
        sm[(i >> 10) * 1025 + (i & 1023)] = v;
        s += v; ss += v * v;
    }
    __shared__ float shs[8], shss[8], stats[2];
    for (int o = 16; o > 0; o >>= 1) { s += __shfl_xor_sync(~0u, s, o); ss += __shfl_xor_sync(~0u, ss, o); }
    if ((tid & 31) == 0) { shs[tid >> 5] = s; shss[tid >> 5] = ss; }
    __syncthreads();
    if (tid < 8) {
        s = shs[tid]; ss = shss[tid];
        for (int o = 4; o > 0; o >>= 1) { s += __shfl_xor_sync(0xff, s, o); ss += __shfl_xor_sync(0xff, ss, o); }
        if (tid == 0) {
            float mu = s * (1.f / (CPG * Nsp));
            float var = ss * (1.f / (CPG * Nsp)) - mu * mu;
            stats[0] = mu; stats[1] = rsqrtf(var + EPSf);
        }
    }
    __syncthreads();
    float mu = stats[0], inv = stats[1];
    int c = tid & 15;
    float gam = gamma[g * CPG + c] * inv;
    float bet = beta[g * CPG + c] - mu * gam;
    __half* hb = g_hn + (size_t)b * Nsp * Cch + g * CPG;
    const float* src = sm + c * 1025;
    for (int j = tid; j < CPG * Nsp; j += 256) {
        int n = j >> 4;
        hb[(size_t)n * Cch + c] = __float2half_rn(src[n] * gam + bet);
    }
}

// ---------------- weight transpose: Wt[d][c] = fp16(sc * W[c][d]) ------------
__global__ void __launch_bounds__(256) wt_kernel(const float* __restrict__ W0, const float* __restrict__ W1,
                                                 const float* __restrict__ W2, const float* __restrict__ W3) {
    __shared__ float t[32][33];
    int w = blockIdx.z;
    const float* src = (w == 0) ? W0 : (w == 1) ? W1 : (w == 2) ? W2 : W3;
    float sc = (w == 0) ? SCALE : 1.0f;
    __half* dst = g_wt + (size_t)w * Cch * Cch;
    int c0 = blockIdx.y * 32, d0 = blockIdx.x * 32;
    int tx = threadIdx.x & 31, ty = threadIdx.x >> 5;
    #pragma unroll
    for (int i = 0; i < 4; i++)
        t[ty + i * 8][tx] = sc * src[(size_t)(c0 + ty + i * 8) * Cch + d0 + tx];
    __syncthreads();
    #pragma unroll
    for (int i = 0; i < 4; i++)
        dst[(size_t)(d0 + ty + i * 8) * Cch + c0 + tx] = __float2half_rn(t[tx][ty + i * 8]);
}

// ---------------- combined qk bias + rsum zero -------------------------------
__global__ void prep_bias(const float* __restrict__ b0, const float* __restrict__ b1) {
    int j = blockIdx.x * 256 + threadIdx.x;
    if (j < 1024) g_bqk[j] = (j < 512) ? SCALE * b0[j] : b1[j - 512];
    if (j < Bsz * Nsp) g_rsum[j] = 0.f;
}

// ---------------- mma.sync GEMM: D[m][n'] = sum_k A[m][k]*B[n'][k] -----------
// CTA 128x128, BK=64 halves (128B rows, xor-swizzled), 8 warps 32x64 each.
// 3-stage cp.async pipeline + explicit ldmatrix fragment double-buffering.
struct GArgs {
    const __half* A; const __half* B; void* D;
    const float* bias; const float* res;
    long long sA, sB, sD;
    int lda, ldb, ldd, K;
    int b0;    // global batch offset (rsum indexing only)
};

#define M_EXP    0   // fp16, exp(v); row sums atomically into g_rsum
#define M_QK     1   // fp16, v + bias[col]
#define M_V      2   // fp16, v + bias[row]
#define M_AV     3   // fp16, v * (1/rsum[row])
#define M_FINAL  4   // fp32, v + bias[row] + res

#define STAGE_BYTES 32768

template<int MODE>
__global__ void __launch_bounds__(256, 2) gemm_mma(const GArgs p) {
    extern __shared__ char smem[];
    const uint32_t sb = smem_u32(smem);
    const int tid = threadIdx.x, lane = tid & 31, wid = tid >> 5;
    const int wm = wid & 3, wn = wid >> 2;
    const int bz = blockIdx.z;
    const int M0 = blockIdx.y * 128, N0 = blockIdx.x * 128;

    // gmem->smem loader mapping: thread -> (row, 4 chunks of 16B)
    const int lr  = tid >> 1;
    const int lcb = (tid & 1) * 4;
    const __half* Ag = p.A + (long long)bz * p.sA + (long long)(M0 + lr) * p.lda;
    const __half* Bg = p.B + (long long)bz * p.sB + (long long)(N0 + lr) * p.ldb;
    const uint32_t rsw = (uint32_t)(lr & 7);
    const uint32_t sArow = sb + lr * 128;
    const uint32_t sBrow = sb + 16384 + lr * 128;

    // ldmatrix per-thread address components
    const int rA0 = wm * 32 + (lane & 15);
    const int cA0 = (lane >> 4);
    const int rB0 = wn * 64 + ((lane >> 4) << 3) + (lane & 7);
    const int cB0 = ((lane >> 3) & 1);

    float acc[2][8][4];
    #pragma unroll
    for (int i = 0; i < 2; i++)
        #pragma unroll
        for (int j = 0; j < 8; j++)
            #pragma unroll
            for (int q = 0; q < 4; q++) acc[i][j][q] = 0.f;

    const int S = p.K >> 6;

    // prefetch stages 0 and 1
    #pragma unroll
    for (int st = 0; st < 2; st++) {
        const __half* ga = Ag + st * 64;
        const __half* gb = Bg + st * 64;
        uint32_t oA = sArow + st * STAGE_BYTES;
        uint32_t oB = sBrow + st * STAGE_BYTES;
        #pragma unroll
        for (int i = 0; i < 4; i++) {
            int c = lcb + i;
            uint32_t sw = ((uint32_t)c ^ rsw) << 4;
            CP16(oA + sw, ga + c * 8);
            CP16(oB + sw, gb + c * 8);
        }
        CPCOMMIT();
    }

    uint32_t afr[2][2][4], bfr[2][4][4];

#define LOADF(ks, A0, B0, af, bf) do {                                              \
    _Pragma("unroll")                                                               \
    for (int mt = 0; mt < 2; mt++) {                                                \
        int row = rA0 + mt * 16;                                                    \
        LDSM4((af)[mt], (A0) + row * 128 +                                          \
              ((uint32_t)((cA0 + 2 * (ks)) ^ (row & 7)) << 4));                     \
    }                                                                               \
    _Pragma("unroll")                                                               \
    for (int pp = 0; pp < 4; pp++) {                                                \
        int row = rB0 + pp * 16;                                                    \
        LDSM4((bf)[pp], (B0) + row * 128 +                                          \
              ((uint32_t)((cB0 + 2 * (ks)) ^ (row & 7)) << 4));                     \
    }                                                                               \
} while (0)

    int buf = 0;
    for (int s = 0; s < S; s++) {
        if (s + 1 < S) { CPWAIT1(); } else { CPWAIT0(); }
        __syncthreads();

        // prefetch stage s+2 into the buffer freed at stage s-1
        if (s + 2 < S) {
            int nb = buf + 2; if (nb >= 3) nb -= 3;
            const __half* ga = Ag + (s + 2) * 64;
            const __half* gb = Bg + (s + 2) * 64;
            uint32_t oA = sArow + nb * STAGE_BYTES;
            uint32_t oB = sBrow + nb * STAGE_BYTES;
            #pragma unroll
            for (int i = 0; i < 4; i++) {
                int c = lcb + i;
                uint32_t sw = ((uint32_t)c ^ rsw) << 4;
                CP16(oA + sw, ga + c * 8);
                CP16(oB + sw, gb + c * 8);
            }
            CPCOMMIT();
        }

        uint32_t A0 = sb + buf * STAGE_BYTES;
        uint32_t B0 = A0 + 16384;

        LOADF(0, A0, B0, afr[0], bfr[0]);
        #pragma unroll
        for (int ks = 0; ks < 4; ks++) {
            int cur = ks & 1;
            if (ks < 3) LOADF(ks + 1, A0, B0, afr[cur ^ 1], bfr[cur ^ 1]);
            #pragma unroll
            for (int mt = 0; mt < 2; mt++)
                #pragma unroll
                for (int nt = 0; nt < 8; nt++)
                    MMA16816(acc[mt][nt], afr[cur][mt],
                             bfr[cur][nt >> 1][(nt & 1) * 2],
                             bfr[cur][nt >> 1][(nt & 1) * 2 + 1]);
        }
        buf++; if (buf >= 3) buf = 0;
    }

    // ------------- epilogue -------------
    const int mbase = M0 + wm * 32 + (lane >> 2);
    const int nbase = N0 + wn * 64 + (lane & 3) * 2;
    const int brs = (bz + p.b0) * Nsp;
    #pragma unroll
    for (int mt = 0; mt < 2; mt++) {
        int r0 = mbase + mt * 16, r1 = r0 + 8;
        float bi0 = 0.f, bi1 = 0.f;
        if (MODE == M_V || MODE == M_FINAL) { bi0 = __ldg(&p.bias[r0]); bi1 = __ldg(&p.bias[r1]); }
        if (MODE == M_AV) {
            bi0 = 1.0f / __ldg(&g_rsum[brs + r0]);
            bi1 = 1.0f / __ldg(&g_rsum[brs + r1]);
        }
        float s0 = 0.f, s1 = 0.f;   // M_EXP partial row sums
        #pragma unroll
        for (int nt = 0; nt < 8; nt++) {
            int cc = nbase + nt * 8;
            float v0 = acc[mt][nt][0], v1 = acc[mt][nt][1];
            float v2 = acc[mt][nt][2], v3 = acc[mt][nt][3];
            if (MODE == M_EXP) {
                __half* Dh = (__half*)p.D + (long long)bz * p.sD;
                float e0 = __expf(v0), e1 = __expf(v1);
                float e2 = __expf(v2), e3 = __expf(v3);
                *(__half2*)(Dh + (size_t)r0 * p.ldd + cc) = __floats2half2_rn(e0, e1);
                *(__half2*)(Dh + (size_t)r1 * p.ldd + cc) = __floats2half2_rn(e2, e3);
                s0 += e0 + e1; s1 += e2 + e3;
            } else if (MODE == M_QK) {
                __half* Dh = (__half*)p.D + (long long)bz * p.sD;
                float c0 = __ldg(&p.bias[cc]), c1 = __ldg(&p.bias[cc + 1]);
                *(__half2*)(Dh + (size_t)r0 * p.ldd + cc) = __floats2half2_rn(v0 + c0, v1 + c1);
                *(__half2*)(Dh + (size_t)r1 * p.ldd + cc) = __floats2half2_rn(v2 + c0, v3 + c1);
            } else if (MODE == M_V) {
                __half* Dh = (__half*)p.D + (long long)bz * p.sD;
                *(__half2*)(Dh + (size_t)r0 * p.ldd + cc) = __floats2half2_rn(v0 + bi0, v1 + bi0);
                *(__half2*)(Dh + (size_t)r1 * p.ldd + cc) = __floats2half2_rn(v2 + bi1, v3 + bi1);
            } else if (MODE == M_AV) {
                __half* Dh = (__half*)p.D + (long long)bz * p.sD;
                *(__half2*)(Dh + (size_t)r0 * p.ldd + cc) = __floats2half2_rn(v0 * bi0, v1 * bi0);
                *(__half2*)(Dh + (size_t)r1 * p.ldd + cc) = __floats2half2_rn(v2 * bi1, v3 * bi1);
            } else {
                float* Dp = (float*)p.D + (long long)bz * p.sD;
                const float* Rp = p.res + (long long)bz * p.sD;
                float2 x0 = *(const float2*)(Rp + (size_t)r0 * p.ldd + cc);
                float2 x1 = *(const float2*)(Rp + (size_t)r1 * p.ldd + cc);
                *(float2*)(Dp + (size_t)r0 * p.ldd + cc) = make_float2(v0 + bi0 + x0.x, v1 + bi0 + x0.y);
                *(float2*)(Dp + (size_t)r1 * p.ldd + cc) = make_float2(v2 + bi1 + x1.x, v3 + bi1 + x1.y);
            }
        }
        if (MODE == M_EXP) {
            s0 += __shfl_xor_sync(~0u, s0, 1); s0 += __shfl_xor_sync(~0u, s0, 2);
            s1 += __shfl_xor_sync(~0u, s1, 1); s1 += __shfl_xor_sync(~0u, s1, 2);
            if ((lane & 3) == 0) {
                atomicAdd(&g_rsum[brs + r0], s0);
                atomicAdd(&g_rsum[brs + r1], s1);
            }
        }
    }
}

// ---------------- launch -----------------------------------------------------
#define GEMM_SMEM (3 * STAGE_BYTES)
#define BH 8   // batches per half (EXP/AV/FINAL pipelining)

extern "C" void kernel_launch(void* const* d_in, const int* in_sizes, int n_in,
                              void* d_out, int out_size) {
    const float* x     = (const float*)d_in[0];
    const float* gamma = (const float*)d_in[1];
    const float* beta  = (const float*)d_in[2];
    const float* W0 = (const float*)d_in[3];  const float* b0 = (const float*)d_in[4];
    const float* W1 = (const float*)d_in[5];  const float* b1 = (const float*)d_in[6];
    const float* W2 = (const float*)d_in[7];  const float* b2 = (const float*)d_in[8];
    const float* W3 = (const float*)d_in[9];  const float* b3 = (const float*)d_in[10];
    float* out = (float*)d_out;

    void *hn_, *qk_, *v_, *o_, *attnh_, *wt_, *bqk_;
    cudaGetSymbolAddress(&hn_, g_hn);
    cudaGetSymbolAddress(&qk_, g_qk);
    cudaGetSymbolAddress(&v_, g_v);
    cudaGetSymbolAddress(&o_, g_o);
    cudaGetSymbolAddress(&attnh_, g_attnh);
    cudaGetSymbolAddress(&wt_, g_wt);
    cudaGetSymbolAddress(&bqk_, g_bqk);
    const __half* hn = (const __half*)hn_;
    const __half* qk = (const __half*)qk_;
    const __half* v  = (const __half*)v_;
    const __half* o  = (const __half*)o_;
    const __half* attnh = (const __half*)attnh_;
    const __half* wt = (const __half*)wt_;
    const float* bqk = (const float*)bqk_;

    cudaFuncSetAttribute(gn_fused,           cudaFuncAttributeMaxDynamicSharedMemorySize, GN_SMEM);
    cudaFuncSetAttribute(gemm_mma<M_EXP>,    cudaFuncAttributeMaxDynamicSharedMemorySize, GEMM_SMEM);
    cudaFuncSetAttribute(gemm_mma<M_QK>,     cudaFuncAttributeMaxDynamicSharedMemorySize, GEMM_SMEM);
    cudaFuncSetAttribute(gemm_mma<M_V>,      cudaFuncAttributeMaxDynamicSharedMemorySize, GEMM_SMEM);
    cudaFuncSetAttribute(gemm_mma<M_AV>,     cudaFuncAttributeMaxDynamicSharedMemorySize, GEMM_SMEM);
    cudaFuncSetAttribute(gemm_mma<M_FINAL>,  cudaFuncAttributeMaxDynamicSharedMemorySize, GEMM_SMEM);

    const long long SNC = (long long)Nsp * Cch;      // 524288
    const long long SQK = (long long)Nsp * 1024;     // 1048576
    const long long SNN = (long long)Nsp * Nsp;      // 1048576

    cudaStream_t s1 = g_as.s1;

    // fork: s1 joins the capture via event from origin stream
    cudaEventRecord(g_as.evA, 0);
    cudaStreamWaitEvent(s1, g_as.evA, 0);

    // s1: weight transpose + bias/rsum prep (independent of x)
    wt_kernel<<<dim3(16, 16, 4), 256, 0, s1>>>(W0, W1, W2, W3);
    prep_bias<<<64, 256, 0, s1>>>(b0, b1);
    cudaEventRecord(g_as.ev_wt, s1);

    // origin: GroupNorm (all batches)
    gn_fused<<<Bsz * Gg, 256, GN_SMEM>>>(x, gamma, beta);
    cudaEventRecord(g_as.ev_gn, 0);

    GArgs a;

    // s1: v[d][n] = W2t @ hn^T + b2[d]  (needs wt [in s1 order] + hn)
    cudaStreamWaitEvent(s1, g_as.ev_gn, 0);
    a = { wt + (size_t)2 * Cch * Cch, hn, (void*)v, b2, nullptr,
          0, SNC, SNC, Cch, Cch, Nsp, Cch, 0 };
    gemm_mma<M_V><<<dim3(8, 4, Bsz), 256, GEMM_SMEM, s1>>>(a);
    cudaEventRecord(g_as.ev_v, s1);

    // origin: qk projection (needs hn [in-order] + wt/bqk/rsum from s1)
    cudaStreamWaitEvent(0, g_as.ev_wt, 0);
    a = { hn, wt, (void*)qk, bqk, nullptr,
          SNC, 0, SQK, Cch, Cch, 1024, Cch, 0 };
    gemm_mma<M_QK><<<dim3(8, 8, Bsz), 256, GEMM_SMEM>>>(a);
    cudaEventRecord(g_as.ev_qk, 0);

    // ---- EXP/AV/FINAL pipelined across batch halves ----
    // origin: half 0 — EXP0 -> AV0 -> FINAL0 (rsum/attnh in-stream)
    a = { qk, qk + 512, (void*)attnh, nullptr, nullptr,
          SQK, SQK, SNN, 1024, 1024, Nsp, Cch, 0 };
    gemm_mma<M_EXP><<<dim3(8, 8, BH), 256, GEMM_SMEM>>>(a);

    cudaStreamWaitEvent(0, g_as.ev_v, 0);   // AV0 needs v from s1
    a = { attnh, v, (void*)o, nullptr, nullptr,
          SNN, SNC, SNC, Nsp, Nsp, Cch, Nsp, 0 };
    gemm_mma<M_AV><<<dim3(4, 8, BH), 256, GEMM_SMEM>>>(a);
    a = { wt + (size_t)3 * Cch * Cch, o, (void*)out, b3, x,
          0, SNC, SNC, Cch, Cch, Nsp, Cch, 0 };
    gemm_mma<M_FINAL><<<dim3(8, 4, BH), 256, GEMM_SMEM>>>(a);

    // s1: half 1 — (after V in-stream) wait qk, then EXP1 -> AV1 -> FINAL1
    cudaStreamWaitEvent(s1, g_as.ev_qk, 0);
    a = { qk + (long long)BH * SQK, qk + (long long)BH * SQK + 512,
          (void*)(attnh + (long long)BH * SNN), nullptr, nullptr,
          SQK, SQK, SNN, 1024, 1024, Nsp, Cch, BH };
    gemm_mma<M_EXP><<<dim3(8, 8, BH), 256, GEMM_SMEM, s1>>>(a);
    a = { attnh + (long long)BH * SNN, v + (long long)BH * SNC,
          (void*)(o + (long long)BH * SNC), nullptr, nullptr,
          SNN, SNC, SNC, Nsp, Nsp, Cch, Nsp, BH };
    gemm_mma<M_AV><<<dim3(4, 8, BH), 256, GEMM_SMEM, s1>>>(a);
    a = { wt + (size_t)3 * Cch * Cch, o + (long long)BH * SNC,
          (void*)(out + (long long)BH * SNC), b3, x + (long long)BH * SNC,
          0, SNC, SNC, Cch, Cch, Nsp, Cch, BH };
    gemm_mma<M_FINAL><<<dim3(8, 4, BH), 256, GEMM_SMEM, s1>>>(a);

    // join s1 back into origin
    cudaEventRecord(g_as.ev_s1done, s1);
    cudaStreamWaitEvent(0, g_as.ev_s1done, 0);
}